// round 12
// baseline (speedup 1.0000x reference)
#include <cuda_runtime.h>
#include <cstdint>

#define SIZE   128
#define EPSF   1e-6f
#define BW     4            // half bandwidth of final operators
#define TAPS   9            // 2*BW+1
#define CW     12           // padded Lb coeff row width
#define SBW    5            // single-sweep inverse band half-width
#define GW     11           // 2*SBW+1
#define KBC    10           // chain band half-width (5-sweep products)
#define CBW    21           // chain band storage width
#define KBE    12           // E (10-sweep) band half-width
#define EW     25           // E band storage width

// ---------------------------------------------------------------------------
// Globals
// ---------------------------------------------------------------------------
__device__ float g_gb[30][SIZE * GW];      // per-sweep banded inverses (hw 5)
__device__ float g_Lb[SIZE * CW];          // row-major padded
__device__ float g_WbT[TAPS * SIZE];       // tap-major: WbT[d][j] = W[j-BW+d][j]

// ---------------------------------------------------------------------------
// mega_setup: ONE CTA, 1024 threads, all phases fused.
// Sweeps s=0..19: X (m0=s, k=m0>>1, t=(k+(m0&1))*DT, dt=DT/2);
// s=20..29: Y (m0=s-20, t=m0*DT+DT/2, dt=DT).
// Chain parts 0..3 = X chains C1..C4 (W=C1*C2*C3*C4), 4..5 = Q1,Q2 (L=Q2*Q1).
// ---------------------------------------------------------------------------
#define COP 129                        // co pitch (conflict-free theta/phi reads)
#define SM_CO   0
#define SM_TH   (SM_CO + 30 * COP)     // th[s*130+i] = theta_{i-1}
#define SM_PH   (SM_TH + 30 * 130)     // ph[s*130+j] = phi_j
#define SM_ACC  (SM_PH + 30 * 130)     // 6 * 128 * CBW
#define SM_E    (SM_ACC + 6 * SIZE * CBW)
#define SM_TOT  (SM_E + 2 * SIZE * EW) // floats

__global__ void __launch_bounds__(1024, 1)
mega_setup_kernel(const float* __restrict__ abx, const float* __restrict__ atx,
                  const float* __restrict__ aqx, const float* __restrict__ bby,
                  const float* __restrict__ bty, const float* __restrict__ bqy)
{
    extern __shared__ float sh[];
    float* co  = sh + SM_CO;
    float* th  = sh + SM_TH;
    float* ph  = sh + SM_PH;
    float* acc = sh + SM_ACC;
    float* E   = sh + SM_E;
    const int tid = threadIdx.x;

    // ---- Phase 1: coefficients for all 30 sweeps (parallel) ----
    for (int idx = tid; idx < 30 * SIZE; idx += 1024) {
        int s = idx >> 7, i = idx & 127;
        bool isY = s >= 20;
        int m0 = isY ? s - 20 : s;
        float t, dt; const float *bp, *lp, *qp;
        if (isY) { t = m0 * 0.01f + 0.005f;                     dt = 0.01f;  bp = bby; lp = bty; qp = bqy; }
        else     { int k = m0 >> 1; t = (k + (m0 & 1)) * 0.01f; dt = 0.005f; bp = abx; lp = atx; qp = aqx; }
        int im = max(i - 1, 0), ip = min(i + 1, 127);
        float vm = fmaxf(bp[im] + lp[im] * t + qp[im] * t * t, EPSF);
        float vc = fmaxf(bp[i]  + lp[i]  * t + qp[i]  * t * t, EPSF);
        float vp = fmaxf(bp[ip] + lp[ip] * t + qp[ip] * t * t, EPSF);
        co[s * COP + i] = (vm + vc + vp) * (1.0f / 3.0f) * dt;
    }
    __syncthreads();

    // ---- Phase 2: theta (warp 0, lanes 0..29) and phi (warp 1, lanes 0..29) ----
    if (tid < 30) {
        const int s = tid;
        const float* c = &co[s * COP];
        float t2 = 1.0f;
        float cprev = c[0];
        float t1 = 1.0f + cprev;
        th[s * 130 + 0] = 1.0f;
        th[s * 130 + 1] = t1;
        for (int r = 1; r < SIZE; r++) {
            float cr = c[r];
            float br = (r == SIZE - 1) ? (1.0f + cr) : (1.0f + 2.0f * cr);
            float tn = br * t1 - (cr * cprev) * t2;
            th[s * 130 + r + 1] = tn;
            t2 = t1; t1 = tn; cprev = cr;
        }
    } else if (tid >= 32 && tid < 62) {
        const int s = tid - 32;
        const float* c = &co[s * COP];
        float p2 = 1.0f;
        float cnext = c[SIZE - 1];
        float p1 = 1.0f + cnext;
        ph[s * 130 + SIZE] = 1.0f;
        ph[s * 130 + SIZE - 1] = p1;
        for (int r = SIZE - 2; r >= 0; r--) {
            float cr = c[r];
            float br = (r == 0) ? (1.0f + cr) : (1.0f + 2.0f * cr);
            float pn = br * p1 - (cr * cnext) * p2;
            ph[s * 130 + r] = pn;
            p2 = p1; p1 = pn; cnext = cr;
        }
    }
    __syncthreads();

    // ---- Phase 3: banded inverses -> g_gb (global; block-visible) ----
    for (int idx = tid; idx < 30 * SIZE; idx += 1024) {
        int s = idx >> 7, i = idx & 127;
        const float invthn = 1.0f / th[s * 130 + SIZE];
        #pragma unroll 1
        for (int e = 0; e < GW; e++) {
            int j = i - SBW + e;
            float g = 0.0f;
            if (j >= 0 && j < SIZE) {
                float prod = 1.0f;
                if (i <= j) {
                    for (int k = i; k < j; k++) prod *= co[s * COP + k];
                    g = prod * th[s * 130 + i] * ph[s * 130 + j + 1] * invthn;
                } else {
                    for (int k = j + 1; k <= i; k++) prod *= co[s * COP + k];
                    g = prod * th[s * 130 + j] * ph[s * 130 + i + 1] * invthn;
                }
            }
            g_gb[s][i * GW + e] = g;
        }
    }
    __syncthreads();

    // ---- Phase 4: chain compositions (6 parts x 128 rows, threads 0..767) ----
    const bool act = tid < 6 * SIZE;
    const int part = tid >> 7, r = tid & 127;
    const bool isY = part >= 4;
    const int base = isY ? 20 + (part - 4) * 5 : part * 5;
    float* ap = &acc[part * SIZE * CBW];

    if (act) {
        #pragma unroll 1
        for (int o = 0; o < CBW; o++) {
            int c = r - KBC + o;
            float v = 0.0f;
            if (c >= 0 && c < SIZE && c - r >= -SBW && c - r <= SBW)
                v = isY ? g_gb[base][r * GW + (c - r + SBW)]
                        : g_gb[base][c * GW + (r - c + SBW)];
            ap[r * CBW + o] = v;
        }
    }
    __syncthreads();

    for (int q = 1; q < 5; q++) {
        float nw[CBW];
        if (act) {
            #pragma unroll 1
            for (int o = 0; o < CBW; o++) {
                int c = r - KBC + o;
                float s = 0.0f;
                if (c >= 0 && c < SIZE) {
                    if (isY) {
                        int klo = max(r - SBW, max(c - KBC, 0));
                        int khi = min(r + SBW, min(c + KBC, SIZE - 1));
                        for (int k = klo; k <= khi; k++)
                            s += g_gb[base + q][r * GW + (k - r + SBW)]
                               * ap[k * CBW + (c - k + KBC)];
                    } else {
                        int klo = max(c - SBW, max(r - KBC, 0));
                        int khi = min(c + SBW, min(r + KBC, SIZE - 1));
                        for (int k = klo; k <= khi; k++)
                            s += ap[r * CBW + (k - r + KBC)]
                               * g_gb[base + q][c * GW + (k - c + SBW)];
                    }
                }
                nw[o] = s;
            }
        }
        __syncthreads();
        if (act) {
            #pragma unroll 1
            for (int o = 0; o < CBW; o++) ap[r * CBW + o] = nw[o];
        }
        __syncthreads();
    }

    // ---- Phase 5: E1 = C1*C2, E2 = C3*C4 (band KBE) ----
    for (int idx = tid; idx < 2 * SIZE * EW; idx += 1024) {
        int e = idx / (SIZE * EW);
        int rem = idx - e * (SIZE * EW);
        int rr = rem / EW, d = rem - rr * EW;
        int c = rr - KBE + d;
        float s = 0.0f;
        if (c >= 0 && c < SIZE) {
            const float* A = &acc[(2 * e)     * SIZE * CBW];
            const float* B = &acc[(2 * e + 1) * SIZE * CBW];
            int klo = max(max(rr, c) - KBC, 0), khi = min(min(rr, c) + KBC, 127);
            for (int k = klo; k <= khi; k++)
                s += A[rr * CBW + (k - rr + KBC)] * B[k * CBW + (c - k + KBC)];
        }
        E[idx] = s;
    }

    // ---- Phase 6a: Lb = band_BW(Q2*Q1) ----
    for (int idx = tid; idx < SIZE * CW; idx += 1024) {
        int i = idx / CW, d = idx - i * CW;
        float s = 0.0f;
        if (d < TAPS) {
            int c = i - BW + d;
            if (c >= 0 && c < SIZE) {
                const float* Q2 = &acc[5 * SIZE * CBW];
                const float* Q1 = &acc[4 * SIZE * CBW];
                int klo = max(max(i, c) - KBC, 0), khi = min(min(i, c) + KBC, 127);
                for (int k = klo; k <= khi; k++)
                    s += Q2[i * CBW + (k - i + KBC)] * Q1[k * CBW + (c - k + KBC)];
            }
        }
        g_Lb[idx] = s;
    }
    __syncthreads();

    // ---- Phase 6b: WbT[d][j] = (E1*E2)[j-BW+d][j] ----
    for (int idx = tid; idx < SIZE * TAPS; idx += 1024) {
        int d = idx / SIZE, j = idx - d * SIZE;
        float s = 0.0f;
        int rr = j - BW + d;
        if (rr >= 0 && rr < SIZE) {
            const float* E1 = E, *E2 = E + SIZE * EW;
            int mlo = max(max(rr, j) - KBE, 0), mhi = min(min(rr, j) + KBE, 127);
            for (int m = mlo; m <= mhi; m++)
                s += E1[rr * EW + (m - rr + KBE)] * E2[m * EW + (j - m + KBE)];
        }
        g_WbT[idx] = s;
    }
}

// ---------------------------------------------------------------------------
// band_kernel: ONE CTA per image (no halo), 256 threads, 8 warps x 16 rows,
// 2 CTAs/SM. Register sliding window (9 float4), Lb warp-uniform LDG,
// Wb in 36 regs (tap-major).
// ---------------------------------------------------------------------------
__device__ __forceinline__ float4 f4fma(float c, float4 w, float4 a) {
    a.x = fmaf(c, w.x, a.x); a.y = fmaf(c, w.y, a.y);
    a.z = fmaf(c, w.z, a.z); a.w = fmaf(c, w.w, a.w);
    return a;
}

__global__ void __launch_bounds__(256, 2)
band_kernel(const float* __restrict__ uin, float* __restrict__ uout)
{
    extern __shared__ float us[];            // 128*128 floats = 64KB

    const int tid  = threadIdx.x, w = tid >> 5, lane = tid & 31;
    const size_t off = (size_t)blockIdx.x * (SIZE * SIZE);
    const float* src = uin + off;

    // stage full image (coalesced float4)
    const float4* src4 = (const float4*)src;
    #pragma unroll
    for (int q = 0; q < 16; q++) {
        int m = tid + q * 256;
        int r = m >> 5, c4 = (m & 31) * 4;
        *(float4*)&us[r * SIZE + c4] = src4[m];
    }

    // per-lane Wb registers, tap-major (cols 4*lane..4*lane+3 per tap)
    float4 wb4[TAPS];
    #pragma unroll
    for (int d = 0; d < TAPS; d++)
        wb4[d] = *(const float4*)&g_WbT[d * SIZE + 4 * lane];
    __syncthreads();

    const int il0 = w * 16;
    float4 win[TAPS];
    #pragma unroll
    for (int t = 0; t < TAPS - 1; t++) {
        int r = max(il0 - BW + t, 0);        // clamp: edge coeffs are zero
        win[t] = *(const float4*)&us[r * SIZE + 4 * lane];
    }

    float* dst = uout + off;
    #pragma unroll
    for (int rr = 0; rr < 16; rr++) {
        int rn = min(il0 + rr + BW, SIZE - 1);
        win[(rr + TAPS - 1) % TAPS] = *(const float4*)&us[rn * SIZE + 4 * lane];
        const int gi = il0 + rr;

        // ---- pass 1: T row (Lb warp-uniform LDG, L2-resident) ----
        const float* cr = &g_Lb[gi * CW];
        float4 c0 = *(const float4*)cr;
        float4 c1 = *(const float4*)(cr + 4);
        float  c8 = cr[8];
        float4 t4 = make_float4(0.f, 0.f, 0.f, 0.f);
        t4 = f4fma(c0.x, win[(rr + 0) % TAPS], t4);
        t4 = f4fma(c0.y, win[(rr + 1) % TAPS], t4);
        t4 = f4fma(c0.z, win[(rr + 2) % TAPS], t4);
        t4 = f4fma(c0.w, win[(rr + 3) % TAPS], t4);
        t4 = f4fma(c1.x, win[(rr + 4) % TAPS], t4);
        t4 = f4fma(c1.y, win[(rr + 5) % TAPS], t4);
        t4 = f4fma(c1.z, win[(rr + 6) % TAPS], t4);
        t4 = f4fma(c1.w, win[(rr + 7) % TAPS], t4);
        t4 = f4fma(c8,   win[(rr + 8) % TAPS], t4);

        // ---- pass 2: row stencil via shuffles (edges hit zero coeffs) ----
        float Tl[12];
        Tl[0] = __shfl_up_sync(0xffffffffu, t4.x, 1);
        Tl[1] = __shfl_up_sync(0xffffffffu, t4.y, 1);
        Tl[2] = __shfl_up_sync(0xffffffffu, t4.z, 1);
        Tl[3] = __shfl_up_sync(0xffffffffu, t4.w, 1);
        Tl[4] = t4.x; Tl[5] = t4.y; Tl[6] = t4.z; Tl[7] = t4.w;
        Tl[8]  = __shfl_down_sync(0xffffffffu, t4.x, 1);
        Tl[9]  = __shfl_down_sync(0xffffffffu, t4.y, 1);
        Tl[10] = __shfl_down_sync(0xffffffffu, t4.z, 1);
        Tl[11] = __shfl_down_sync(0xffffffffu, t4.w, 1);

        float4 o = make_float4(0.f, 0.f, 0.f, 0.f);
        #pragma unroll
        for (int d = 0; d < TAPS; d++) {
            o.x = fmaf(wb4[d].x, Tl[0 + d], o.x);
            o.y = fmaf(wb4[d].y, Tl[1 + d], o.y);
            o.z = fmaf(wb4[d].z, Tl[2 + d], o.z);
            o.w = fmaf(wb4[d].w, Tl[3 + d], o.w);
        }
        *(float4*)&dst[gi * SIZE + 4 * lane] = o;
    }
}

// ---------------------------------------------------------------------------
extern "C" void kernel_launch(void* const* d_in, const int* in_sizes, int n_in,
                              void* d_out, int out_size)
{
    const float* u   = (const float*)d_in[0];
    const float* abx = (const float*)d_in[1];
    const float* bby = (const float*)d_in[4];
    const float* atx = (const float*)d_in[5];
    const float* bty = (const float*)d_in[8];
    const float* aqx = (const float*)d_in[9];
    const float* bqy = (const float*)d_in[12];
    float* out = (float*)d_out;

    const int smem_setup = SM_TOT * (int)sizeof(float);          // ~137 KB
    const int smem_band  = SIZE * SIZE * (int)sizeof(float);     // 65536

    cudaFuncSetAttribute(mega_setup_kernel, cudaFuncAttributeMaxDynamicSharedMemorySize, smem_setup);
    cudaFuncSetAttribute(band_kernel,       cudaFuncAttributeMaxDynamicSharedMemorySize, smem_band);

    const int batch = out_size / (SIZE * SIZE);   // 2048

    mega_setup_kernel<<<1, 1024, smem_setup>>>(abx, atx, aqx, bby, bty, bqy);
    band_kernel<<<batch, 256, smem_band>>>(u, out);
}

// round 13
// speedup vs baseline: 1.3490x; 1.3490x over previous
#include <cuda_runtime.h>
#include <cstdint>

#define SIZE   128
#define EPSF   1e-6f
#define BW     4            // half bandwidth of final operators
#define TAPS   9            // 2*BW+1
#define CW     12           // padded Lb coeff row width
#define SBW    5            // single-sweep inverse band half-width
#define GW     11           // 2*SBW+1
#define KBC    10           // chain band half-width (5-sweep products)
#define CBW    21           // chain band storage width
#define KBE    12           // E (10-sweep) band half-width
#define EW     25           // E band storage width

// ---------------------------------------------------------------------------
// Globals
// ---------------------------------------------------------------------------
__device__ float g_gb[30][SIZE * GW];      // per-sweep banded inverses (hw 5)
// banded chains: 0..3 = X chains C1..C4 (W = C1*C2*C3*C4), 4 = Q1, 5 = Q2 (L = Q2*Q1)
__device__ float g_cb[6][SIZE * CBW];
__device__ float g_Lb[SIZE * CW];          // row-major padded
__device__ float g_WbT[TAPS * SIZE];       // tap-major: WbT[d][j] = W[j-BW+d][j]

// ---------------------------------------------------------------------------
// sweep_inv: grid 150 (5 redundant CTAs per sweep; grid>=148 defeats the
// low-grid issue throttle). Closed-form banded inverse per tridiagonal solve:
//   (M^-1)_{ij} = (Π co) θ_{i-1} φ_{j+1} / θ_{n-1}
// X sweeps s=0..19 (m0=s: k=m0>>1, t=(k+(m0&1))*DT, dt=DT/2);
// Y sweeps s=20..29 (m0=s-20: t=m0*DT+DT/2, dt=DT).
// ---------------------------------------------------------------------------
__global__ void __launch_bounds__(128, 1)
sweep_inv_kernel(const float* __restrict__ abx, const float* __restrict__ atx,
                 const float* __restrict__ aqx, const float* __restrict__ bby,
                 const float* __restrict__ bty, const float* __restrict__ bqy)
{
    __shared__ float co[SIZE];
    __shared__ float th[SIZE + 1];
    __shared__ float ph[SIZE + 1];

    const int s  = blockIdx.x % 30;
    const bool isY = s >= 20;
    const int m0 = isY ? s - 20 : s;
    const int i  = threadIdx.x;

    float t, dt; const float *bp, *lp, *qp;
    if (isY) { t = m0 * 0.01f + 0.005f;                     dt = 0.01f;  bp = bby; lp = bty; qp = bqy; }
    else     { int k = m0 >> 1; t = (k + (m0 & 1)) * 0.01f; dt = 0.005f; bp = abx; lp = atx; qp = aqx; }

    int im = max(i - 1, 0), ip = min(i + 1, 127);
    float vm = fmaxf(bp[im] + lp[im] * t + qp[im] * t * t, EPSF);
    float vc = fmaxf(bp[i]  + lp[i]  * t + qp[i]  * t * t, EPSF);
    float vp = fmaxf(bp[ip] + lp[ip] * t + qp[ip] * t * t, EPSF);
    co[i] = (vm + vc + vp) * (1.0f / 3.0f) * dt;
    __syncthreads();

    if (i == 0) {
        float t2 = 1.0f;
        float cprev = co[0];
        float t1 = 1.0f + cprev;
        th[0] = 1.0f; th[1] = t1;
        for (int r = 1; r < SIZE; r++) {
            float cr = co[r];
            float br = (r == SIZE - 1) ? (1.0f + cr) : (1.0f + 2.0f * cr);
            float tn = br * t1 - (cr * cprev) * t2;
            th[r + 1] = tn;
            t2 = t1; t1 = tn; cprev = cr;
        }
    } else if (i == 64) {
        float p2 = 1.0f;
        float cnext = co[SIZE - 1];
        float p1 = 1.0f + cnext;
        ph[SIZE] = 1.0f; ph[SIZE - 1] = p1;
        for (int r = SIZE - 2; r >= 0; r--) {
            float cr = co[r];
            float br = (r == 0) ? (1.0f + cr) : (1.0f + 2.0f * cr);
            float pn = br * p1 - (cr * cnext) * p2;
            ph[r] = pn;
            p2 = p1; p1 = pn; cnext = cr;
        }
    }
    __syncthreads();

    const float invthn = 1.0f / th[SIZE];
    #pragma unroll 1
    for (int e = 0; e < GW; e++) {
        int j = i - SBW + e;
        float g = 0.0f;
        if (j >= 0 && j < SIZE) {
            float prod = 1.0f;
            if (i <= j) {
                for (int k = i; k < j; k++) prod *= co[k];
                g = prod * th[i] * ph[j + 1] * invthn;
            } else {
                for (int k = j + 1; k <= i; k++) prod *= co[k];
                g = prod * th[j] * ph[i + 1] * invthn;
            }
        }
        g_gb[s][i * GW + e] = g;
    }
}

// ---------------------------------------------------------------------------
// chain: grid 150 (25 redundant CTAs per part). Compose 5 banded inverses.
// X parts 0..3: Acc <- Acc * Gq^T ; Y parts 4..5: Acc <- Gq * Acc
// ---------------------------------------------------------------------------
__global__ void __launch_bounds__(128, 1) chain_kernel()
{
    __shared__ float acc[SIZE * CBW];
    __shared__ float gsm[SIZE * GW];

    const int part = blockIdx.x % 6;
    const bool isY = part >= 4;
    const int base = isY ? 20 + (part - 4) * 5 : part * 5;
    const int r = threadIdx.x;

    for (int m = r; m < SIZE * GW; m += 128) gsm[m] = g_gb[base][m];
    __syncthreads();
    #pragma unroll 1
    for (int o = 0; o < CBW; o++) {
        int c = r - KBC + o;
        float v = 0.0f;
        if (c >= 0 && c < SIZE && c - r >= -SBW && c - r <= SBW)
            v = isY ? gsm[r * GW + (c - r + SBW)]
                    : gsm[c * GW + (r - c + SBW)];
        acc[r * CBW + o] = v;
    }
    __syncthreads();

    #pragma unroll 1
    for (int q = 1; q < 5; q++) {
        for (int m = r; m < SIZE * GW; m += 128) gsm[m] = g_gb[base + q][m];
        __syncthreads();

        float nw[CBW];
        #pragma unroll 1
        for (int o = 0; o < CBW; o++) {
            int c = r - KBC + o;
            float s = 0.0f;
            if (c >= 0 && c < SIZE) {
                if (isY) {
                    int klo = max(r - SBW, max(c - KBC, 0));
                    int khi = min(r + SBW, min(c + KBC, SIZE - 1));
                    for (int k = klo; k <= khi; k++)
                        s += gsm[r * GW + (k - r + SBW)] * acc[k * CBW + (c - k + KBC)];
                } else {
                    int klo = max(c - SBW, max(r - KBC, 0));
                    int khi = min(c + SBW, min(r + KBC, SIZE - 1));
                    for (int k = klo; k <= khi; k++)
                        s += acc[r * CBW + (k - r + KBC)] * gsm[c * GW + (k - c + SBW)];
                }
            }
            nw[o] = s;
        }
        __syncthreads();
        #pragma unroll 1
        for (int o = 0; o < CBW; o++) acc[r * CBW + o] = nw[o];
        __syncthreads();
    }

    for (int o = 0; o < CBW; o++)
        g_cb[part][r * CBW + o] = acc[r * CBW + o];
}

// ---------------------------------------------------------------------------
// setup3: grid 148, all CTAs redundantly compute the final band tables.
// E1 = C1*C2, E2 = C3*C4 (band KBE); Lb = band_BW(Q2*Q1); WbT = band_BW(E1*E2)^T.
// ---------------------------------------------------------------------------
__global__ void __launch_bounds__(1024, 1) setup3_kernel()
{
    extern __shared__ float s3[];
    float* cb = s3;                      // 6*128*21
    float* E  = s3 + 6 * SIZE * CBW;     // 2*128*25
    const int tid = threadIdx.x;

    for (int m = tid; m < 6 * SIZE * CBW; m += 1024)
        cb[m] = ((const float*)g_cb)[m];
    __syncthreads();

    for (int idx = tid; idx < 2 * SIZE * EW; idx += 1024) {
        int e = idx / (SIZE * EW);
        int rem = idx - e * (SIZE * EW);
        int r = rem / EW, d = rem - r * EW;
        int c = r - KBE + d;
        float s = 0.0f;
        if (c >= 0 && c < SIZE) {
            const float* A = cb + (2 * e)     * SIZE * CBW;
            const float* B = cb + (2 * e + 1) * SIZE * CBW;
            int klo = max(max(r, c) - KBC, 0), khi = min(min(r, c) + KBC, 127);
            for (int k = klo; k <= khi; k++)
                s += A[r * CBW + (k - r + KBC)] * B[k * CBW + (c - k + KBC)];
        }
        E[idx] = s;
    }

    // Lb[i][d] = (Q2*Q1)[i][i-BW+d], padded to CW
    for (int idx = tid; idx < SIZE * CW; idx += 1024) {
        int i = idx / CW, d = idx - i * CW;
        float s = 0.0f;
        if (d < TAPS) {
            int c = i - BW + d;
            if (c >= 0 && c < SIZE) {
                const float* Q2 = cb + 5 * SIZE * CBW;
                const float* Q1 = cb + 4 * SIZE * CBW;
                int klo = max(max(i, c) - KBC, 0), khi = min(min(i, c) + KBC, 127);
                for (int k = klo; k <= khi; k++)
                    s += Q2[i * CBW + (k - i + KBC)] * Q1[k * CBW + (c - k + KBC)];
            }
        }
        g_Lb[idx] = s;
    }
    __syncthreads();

    // WbT[d][j] = (E1*E2)[j-BW+d][j]
    for (int idx = tid; idx < SIZE * TAPS; idx += 1024) {
        int d = idx / SIZE, j = idx - d * SIZE;
        float s = 0.0f;
        int r = j - BW + d;
        if (r >= 0 && r < SIZE) {
            const float* E1 = E, *E2 = E + SIZE * EW;
            int mlo = max(max(r, j) - KBE, 0), mhi = min(min(r, j) + KBE, 127);
            for (int m = mlo; m <= mhi; m++)
                s += E1[r * EW + (m - r + KBE)] * E2[m * EW + (j - m + KBE)];
        }
        g_WbT[idx] = s;
    }
}

// ---------------------------------------------------------------------------
// band_kernel (R12 verbatim — measured 53.4us): ONE CTA per image, 256 threads,
// 8 warps x 16 rows, 2 CTAs/SM. Register sliding window (9 float4),
// Lb warp-uniform LDG, Wb in 36 regs (tap-major).
// ---------------------------------------------------------------------------
__device__ __forceinline__ float4 f4fma(float c, float4 w, float4 a) {
    a.x = fmaf(c, w.x, a.x); a.y = fmaf(c, w.y, a.y);
    a.z = fmaf(c, w.z, a.z); a.w = fmaf(c, w.w, a.w);
    return a;
}

__global__ void __launch_bounds__(256, 2)
band_kernel(const float* __restrict__ uin, float* __restrict__ uout)
{
    extern __shared__ float us[];            // 128*128 floats = 64KB

    const int tid  = threadIdx.x, w = tid >> 5, lane = tid & 31;
    const size_t off = (size_t)blockIdx.x * (SIZE * SIZE);
    const float* src = uin + off;

    const float4* src4 = (const float4*)src;
    #pragma unroll
    for (int q = 0; q < 16; q++) {
        int m = tid + q * 256;
        int r = m >> 5, c4 = (m & 31) * 4;
        *(float4*)&us[r * SIZE + c4] = src4[m];
    }

    float4 wb4[TAPS];
    #pragma unroll
    for (int d = 0; d < TAPS; d++)
        wb4[d] = *(const float4*)&g_WbT[d * SIZE + 4 * lane];
    __syncthreads();

    const int il0 = w * 16;
    float4 win[TAPS];
    #pragma unroll
    for (int t = 0; t < TAPS - 1; t++) {
        int r = max(il0 - BW + t, 0);        // clamp: edge coeffs are zero
        win[t] = *(const float4*)&us[r * SIZE + 4 * lane];
    }

    float* dst = uout + off;
    #pragma unroll
    for (int rr = 0; rr < 16; rr++) {
        int rn = min(il0 + rr + BW, SIZE - 1);
        win[(rr + TAPS - 1) % TAPS] = *(const float4*)&us[rn * SIZE + 4 * lane];
        const int gi = il0 + rr;

        const float* cr = &g_Lb[gi * CW];
        float4 c0 = *(const float4*)cr;
        float4 c1 = *(const float4*)(cr + 4);
        float  c8 = cr[8];
        float4 t4 = make_float4(0.f, 0.f, 0.f, 0.f);
        t4 = f4fma(c0.x, win[(rr + 0) % TAPS], t4);
        t4 = f4fma(c0.y, win[(rr + 1) % TAPS], t4);
        t4 = f4fma(c0.z, win[(rr + 2) % TAPS], t4);
        t4 = f4fma(c0.w, win[(rr + 3) % TAPS], t4);
        t4 = f4fma(c1.x, win[(rr + 4) % TAPS], t4);
        t4 = f4fma(c1.y, win[(rr + 5) % TAPS], t4);
        t4 = f4fma(c1.z, win[(rr + 6) % TAPS], t4);
        t4 = f4fma(c1.w, win[(rr + 7) % TAPS], t4);
        t4 = f4fma(c8,   win[(rr + 8) % TAPS], t4);

        float Tl[12];
        Tl[0] = __shfl_up_sync(0xffffffffu, t4.x, 1);
        Tl[1] = __shfl_up_sync(0xffffffffu, t4.y, 1);
        Tl[2] = __shfl_up_sync(0xffffffffu, t4.z, 1);
        Tl[3] = __shfl_up_sync(0xffffffffu, t4.w, 1);
        Tl[4] = t4.x; Tl[5] = t4.y; Tl[6] = t4.z; Tl[7] = t4.w;
        Tl[8]  = __shfl_down_sync(0xffffffffu, t4.x, 1);
        Tl[9]  = __shfl_down_sync(0xffffffffu, t4.y, 1);
        Tl[10] = __shfl_down_sync(0xffffffffu, t4.z, 1);
        Tl[11] = __shfl_down_sync(0xffffffffu, t4.w, 1);

        float4 o = make_float4(0.f, 0.f, 0.f, 0.f);
        #pragma unroll
        for (int d = 0; d < TAPS; d++) {
            o.x = fmaf(wb4[d].x, Tl[0 + d], o.x);
            o.y = fmaf(wb4[d].y, Tl[1 + d], o.y);
            o.z = fmaf(wb4[d].z, Tl[2 + d], o.z);
            o.w = fmaf(wb4[d].w, Tl[3 + d], o.w);
        }
        *(float4*)&dst[gi * SIZE + 4 * lane] = o;
    }
}

// ---------------------------------------------------------------------------
extern "C" void kernel_launch(void* const* d_in, const int* in_sizes, int n_in,
                              void* d_out, int out_size)
{
    const float* u   = (const float*)d_in[0];
    const float* abx = (const float*)d_in[1];
    const float* bby = (const float*)d_in[4];
    const float* atx = (const float*)d_in[5];
    const float* bty = (const float*)d_in[8];
    const float* aqx = (const float*)d_in[9];
    const float* bqy = (const float*)d_in[12];
    float* out = (float*)d_out;

    const int smem_s3   = (6 * SIZE * CBW + 2 * SIZE * EW) * (int)sizeof(float);  // 90112
    const int smem_band = SIZE * SIZE * (int)sizeof(float);                       // 65536

    cudaFuncSetAttribute(setup3_kernel, cudaFuncAttributeMaxDynamicSharedMemorySize, smem_s3);
    cudaFuncSetAttribute(band_kernel,   cudaFuncAttributeMaxDynamicSharedMemorySize, smem_band);

    const int batch = out_size / (SIZE * SIZE);   // 2048

    sweep_inv_kernel<<<150, 128>>>(abx, atx, aqx, bby, bty, bqy);
    chain_kernel<<<150, 128>>>();
    setup3_kernel<<<148, 1024, smem_s3>>>();
    band_kernel<<<batch, 256, smem_band>>>(u, out);
}